// round 9
// baseline (speedup 1.0000x reference)
#include <cuda_runtime.h>
#include <cuda_fp16.h>
#include <cstdint>
#include <cstddef>

// Problem constants
#define NTOK 16384
#define DIN  512
#define DOUT 512
#define NEXP 16

// GEMM tiling (fp16 mma.sync m16n8k16)
#define BM 128
#define BN 128
#define BK 32
#define KSTAGES (DIN / BK)     // 16
#define NSTAGE 4               // cp.async ring depth
#define MAXTILES 272           // sum ceil(cnt_e/128) <= 32768/128 + 16
#define ASTAGE (BM * BK * 2)   // 8192 B
#define BSTAGE (BN * BK * 2)   // 8192 B
#define SMEM_GEMM (NSTAGE * (ASTAGE + BSTAGE) + 1024)   // 66560 B dynamic

// ---------------- device scratch ----------------------------------------------
__device__ int   g_counts[NEXP];
__device__ int   g_tok [NEXP * NTOK];
__device__ int   g_dest[NEXP * NTOK];
__device__ float g_wt  [NEXP * NTOK];
__device__ float g_scratch[(size_t)NTOK * 2 * DOUT];         // 64 MB
__device__ __half g_xh[(size_t)NTOK * DIN];                  // x fp16
__device__ __half g_wth[(size_t)NEXP * DOUT * DIN];          // W^T fp16 [E][DOUT][DIN]

// ---------------- PTX helpers --------------------------------------------------
__device__ __forceinline__ uint32_t smem_u32(const void* p) {
    uint32_t a;
    asm("{ .reg .u64 t; cvta.to.shared.u64 t, %1; cvt.u32.u64 %0, t; }" : "=r"(a) : "l"(p));
    return a;
}
__device__ __forceinline__ void cp16(uint32_t dst, const void* src) {
    asm volatile("cp.async.cg.shared.global [%0], [%1], 16;" :: "r"(dst), "l"(src) : "memory");
}
__device__ __forceinline__ void ldsm_x4(uint32_t* r, uint32_t addr) {
    asm volatile("ldmatrix.sync.aligned.m8n8.x4.shared.b16 {%0,%1,%2,%3}, [%4];"
                 : "=r"(r[0]), "=r"(r[1]), "=r"(r[2]), "=r"(r[3]) : "r"(addr));
}
__device__ __forceinline__ void mma16816(float* d, const uint32_t* a, const uint32_t* b) {
    asm volatile("mma.sync.aligned.m16n8k16.row.col.f32.f16.f16.f32 "
                 "{%0,%1,%2,%3}, {%4,%5,%6,%7}, {%8,%9}, {%0,%1,%2,%3};"
                 : "+f"(d[0]), "+f"(d[1]), "+f"(d[2]), "+f"(d[3])
                 : "r"(a[0]), "r"(a[1]), "r"(a[2]), "r"(a[3]), "r"(b[0]), "r"(b[1]));
}

// ---------------- kernel 0: zero counters -------------------------------------
__global__ void zero_counts_kernel() {
    if (threadIdx.x < NEXP) g_counts[threadIdx.x] = 0;
}

// ---------------- kernel 1: router + fused x->fp16 -----------------------------
// One warp per token. Lane l holds float4 chunk i = s*32 + l of the row.
__global__ void router_kernel(const float* __restrict__ x,
                              const float* __restrict__ gw,
                              const float* __restrict__ gb) {
    int t    = (blockIdx.x * blockDim.x + threadIdx.x) >> 5;
    int lane = threadIdx.x & 31;
    if (t >= NTOK) return;

    const float4* xr4 = reinterpret_cast<const float4*>(x + (size_t)t * DIN);
    __half2*      xh2 = reinterpret_cast<__half2*>(g_xh + (size_t)t * DIN);

    float acc[NEXP];
#pragma unroll
    for (int e = 0; e < NEXP; e++) acc[e] = 0.f;

#pragma unroll
    for (int s = 0; s < DIN / 128; s++) {          // 4 iterations
        int i = s * 32 + lane;                     // float4 index in row
        float4 v = __ldg(xr4 + i);
        xh2[i * 2 + 0] = __floats2half2_rn(v.x, v.y);
        xh2[i * 2 + 1] = __floats2half2_rn(v.z, v.w);
        float vv[4] = {v.x, v.y, v.z, v.w};
#pragma unroll
        for (int j = 0; j < 4; j++) {
            const float4* g4 = reinterpret_cast<const float4*>(gw + (size_t)(i * 4 + j) * NEXP);
            float4 a  = __ldg(g4 + 0);
            float4 b  = __ldg(g4 + 1);
            float4 c  = __ldg(g4 + 2);
            float4 dd = __ldg(g4 + 3);
            float xv = vv[j];
            acc[0]  += xv * a.x;  acc[1]  += xv * a.y;  acc[2]  += xv * a.z;  acc[3]  += xv * a.w;
            acc[4]  += xv * b.x;  acc[5]  += xv * b.y;  acc[6]  += xv * b.z;  acc[7]  += xv * b.w;
            acc[8]  += xv * c.x;  acc[9]  += xv * c.y;  acc[10] += xv * c.z;  acc[11] += xv * c.w;
            acc[12] += xv * dd.x; acc[13] += xv * dd.y; acc[14] += xv * dd.z; acc[15] += xv * dd.w;
        }
    }
#pragma unroll
    for (int e = 0; e < NEXP; e++) {
#pragma unroll
        for (int off = 16; off > 0; off >>= 1)
            acc[e] += __shfl_xor_sync(0xffffffffu, acc[e], off);
    }
    if (lane == 0) {
        float v[NEXP];
#pragma unroll
        for (int e = 0; e < NEXP; e++) v[e] = acc[e] + gb[e];
        float v0 = v[0]; int e0 = 0;
#pragma unroll
        for (int e = 1; e < NEXP; e++) { if (v[e] > v0) { v0 = v[e]; e0 = e; } }
        float v1 = -3.402823466e38f; int e1 = -1;
#pragma unroll
        for (int e = 0; e < NEXP; e++) { if (e != e0 && v[e] > v1) { v1 = v[e]; e1 = e; } }
        float ex  = expf(v1 - v0);
        float inv = 1.f / (1.f + ex);
        int p0 = atomicAdd(&g_counts[e0], 1);
        g_tok [e0 * NTOK + p0] = t;
        g_dest[e0 * NTOK + p0] = 2 * t;
        g_wt  [e0 * NTOK + p0] = inv;
        int p1 = atomicAdd(&g_counts[e1], 1);
        g_tok [e1 * NTOK + p1] = t;
        g_dest[e1 * NTOK + p1] = 2 * t + 1;
        g_wt  [e1 * NTOK + p1] = ex * inv;
    }
}

// ---------------- kernel 2: W -> W^T fp16 (K-major) ---------------------------
__global__ void convert_w_kernel(const float* __restrict__ ew) {
    __shared__ float tile[32][33];
    int e  = blockIdx.z;
    int d0 = blockIdx.y * 32;     // din tile
    int o0 = blockIdx.x * 32;     // dout tile
    int tx = threadIdx.x & 31, ty = threadIdx.x >> 5;       // 32x8 threads
    const float* src = ew + ((size_t)e * DIN + d0) * DOUT + o0;
#pragma unroll
    for (int i = 0; i < 4; i++)
        tile[ty + i * 8][tx] = src[(size_t)(ty + i * 8) * DOUT + tx];
    __syncthreads();
#pragma unroll
    for (int i = 0; i < 4; i++) {
        int r = ty + i * 8;                       // output row (n) within tile
        float v = tile[tx][r];                    // = W[d0+tx][o0+r]
        g_wth[((size_t)e * DOUT + o0 + r) * DIN + d0 + tx] = __float2half_rn(v);
    }
}

// ---------------- kernel 3: grouped GEMM, 4-stage cp.async ring ---------------
__global__ __launch_bounds__(256, 2)
void moe_gemm_kernel(const float* __restrict__ eb) {
    extern __shared__ __align__(16) uint8_t dynsmem[];
    uint8_t* Asm = dynsmem;                                  // NSTAGE * ASTAGE
    uint8_t* Bsm = dynsmem + NSTAGE * ASTAGE;                // NSTAGE * BSTAGE
    int*     stok = reinterpret_cast<int*>(dynsmem + NSTAGE * (ASTAGE + BSTAGE));
    __shared__ int s_e, s_mbase, s_cnt;

    const int tid  = threadIdx.x;
    const int lane = tid & 31;
    const int wid  = tid >> 5;
    const int wm   = (wid & 1) * 64;
    const int wn   = (wid >> 1) * 32;

    if (tid == 0) {
        int b = blockIdx.x, acc = 0, e = -1, mb = 0, cn = 0;
        for (int i = 0; i < NEXP; i++) {
            int c = g_counts[i], t = (c + BM - 1) >> 7;
            if (b < acc + t) { e = i; mb = (b - acc) * BM; cn = c; break; }
            acc += t;
        }
        s_e = e; s_mbase = mb; s_cnt = cn;
    }
    __syncthreads();
    const int e = s_e;
    if (e < 0) return;
    const int mbase = s_mbase, cnt = s_cnt;
    const int nbase = blockIdx.y * BN;

    if (tid < BM) {
        int r = mbase + tid;
        stok[tid] = (r < cnt) ? g_tok[e * NTOK + r] : 0;
    }
    __syncthreads();

    const uint32_t Ab = smem_u32(Asm);
    const uint32_t Bb = smem_u32(Bsm);
    const __half* wtp = g_wth + (size_t)(e * DOUT + nbase) * DIN;

    // cp.async mapping: 512 16B-chunks per tile; thread covers {tid, tid+256}
    auto prefetch = [&](int kt, int buf) {
        int k0 = kt * BK;
#pragma unroll
        for (int t = 0; t < 2; t++) {
            int i = tid + t * 256;
            int r = i >> 2, c = i & 3;
            uint32_t dst = Ab + buf * ASTAGE + r * 64 + ((c ^ ((r >> 1) & 3)) << 4);
            cp16(dst, g_xh + (size_t)stok[r] * DIN + k0 + c * 8);
        }
#pragma unroll
        for (int t = 0; t < 2; t++) {
            int i = tid + t * 256;
            int n = i >> 2, c = i & 3;
            uint32_t dst = Bb + buf * BSTAGE + n * 64 + ((c ^ ((n >> 1) & 3)) << 4);
            cp16(dst, wtp + (size_t)n * DIN + k0 + c * 8);
        }
        asm volatile("cp.async.commit_group;" ::: "memory");
    };

    float acc[4][4][4];
#pragma unroll
    for (int i = 0; i < 4; i++)
#pragma unroll
        for (int j = 0; j < 4; j++)
#pragma unroll
            for (int r = 0; r < 4; r++) acc[i][j][r] = 0.f;

    // lane decomposition for ldmatrix addressing
    const int lrow = (lane & 7) | (((lane >> 3) & 1) << 3);  // row within 16 (A)
    const int akc  = (lane >> 4) & 1;                        // A k-chunk parity
    const int bg   = lane >> 3;                              // B group 0..3
    const int brow = (lane & 7) | ((bg & 2) << 2);           // row within 16 (B)
    const int bkc  = bg & 1;                                 // B k-chunk parity

    prefetch(0, 0);
    prefetch(1, 1);
    prefetch(2, 2);

#pragma unroll 1
    for (int s = 0; s < KSTAGES; s++) {
        int buf = s & 3;
        if (s < KSTAGES - 2)       asm volatile("cp.async.wait_group 2;" ::: "memory");
        else if (s == KSTAGES - 2) asm volatile("cp.async.wait_group 1;" ::: "memory");
        else                       asm volatile("cp.async.wait_group 0;" ::: "memory");
        __syncthreads();   // single barrier per stage: proves ring slot (s-1)&3 drained

        uint32_t abase = Ab + buf * ASTAGE;
        uint32_t bbase = Bb + buf * BSTAGE;
#pragma unroll
        for (int kk = 0; kk < 2; kk++) {
            uint32_t a[4][4];
#pragma unroll
            for (int mf = 0; mf < 4; mf++) {
                int r = wm + mf * 16 + lrow;
                int c = kk * 2 + akc;
                ldsm_x4(a[mf], abase + r * 64 + ((c ^ ((r >> 1) & 3)) << 4));
            }
            uint32_t b[2][4];   // b[p] = frags for nf=2p (regs 0,1) and nf=2p+1 (regs 2,3)
#pragma unroll
            for (int p = 0; p < 2; p++) {
                int n = wn + p * 16 + brow;
                int c = kk * 2 + bkc;
                ldsm_x4(b[p], bbase + n * 64 + ((c ^ ((n >> 1) & 3)) << 4));
            }
#pragma unroll
            for (int mf = 0; mf < 4; mf++)
#pragma unroll
                for (int nf = 0; nf < 4; nf++)
                    mma16816(acc[mf][nf], a[mf], &b[nf >> 1][(nf & 1) * 2]);
        }
        if (s + 3 < KSTAGES) prefetch(s + 3, (s + 3) & 3);
    }

    // ---- epilogue: scale by routing weight, add bias, scatter to unique slot --
    const float* ebp = eb + e * DOUT + nbase;
#pragma unroll
    for (int mf = 0; mf < 4; mf++) {
        int rl0 = wm + mf * 16 + (lane >> 2);
#pragma unroll
        for (int h = 0; h < 2; h++) {
            int r = mbase + rl0 + h * 8;
            if (r < cnt) {
                int dst  = g_dest[e * NTOK + r];
                float w  = g_wt [e * NTOK + r];
                float* outp = g_scratch + (size_t)dst * DOUT + nbase;
#pragma unroll
                for (int nf = 0; nf < 4; nf++) {
                    int n = wn + nf * 8 + (lane & 3) * 2;
                    float b0 = ebp[n], b1 = ebp[n + 1];
                    float2 v;
                    v.x = w * (acc[mf][nf][h * 2 + 0] + b0);
                    v.y = w * (acc[mf][nf][h * 2 + 1] + b1);
                    *reinterpret_cast<float2*>(outp + n) = v;
                }
            }
        }
    }
}

// ---------------- kernel 4: combine -------------------------------------------
__global__ void combine_kernel(float* __restrict__ out) {
    int idx = blockIdx.x * blockDim.x + threadIdx.x;   // float4 index
    int t = idx >> 7;
    int c = idx & 127;
    const float4* s = reinterpret_cast<const float4*>(g_scratch);
    float4 a = s[(size_t)t * 256 + c];
    float4 b = s[(size_t)t * 256 + 128 + c];
    float4 r;
    r.x = a.x + b.x; r.y = a.y + b.y; r.z = a.z + b.z; r.w = a.w + b.w;
    reinterpret_cast<float4*>(out)[idx] = r;
}

// ---------------- launch ------------------------------------------------------
extern "C" void kernel_launch(void* const* d_in, const int* in_sizes, int n_in,
                              void* d_out, int out_size) {
    (void)in_sizes; (void)n_in; (void)out_size;
    const float* x  = (const float*)d_in[0];
    const float* gw = (const float*)d_in[1];
    const float* gb = (const float*)d_in[2];
    const float* ew = (const float*)d_in[3];
    const float* eb = (const float*)d_in[4];
    float* out = (float*)d_out;

    cudaFuncSetAttribute(moe_gemm_kernel,
                         cudaFuncAttributeMaxDynamicSharedMemorySize, SMEM_GEMM);

    zero_counts_kernel<<<1, 32>>>();
    router_kernel<<<NTOK / 8, 256>>>(x, gw, gb);
    convert_w_kernel<<<dim3(DOUT / 32, DIN / 32, NEXP), 256>>>(ew);
    moe_gemm_kernel<<<dim3(MAXTILES, DOUT / BN), 256, SMEM_GEMM>>>(eb);
    combine_kernel<<<(NTOK * DOUT / 4) / 256, 256>>>(out);
}

// round 10
// speedup vs baseline: 1.2760x; 1.2760x over previous
#include <cuda_runtime.h>
#include <cuda_fp16.h>
#include <cstdint>
#include <cstddef>

// Problem constants
#define NTOK 16384
#define DIN  512
#define DOUT 512
#define NEXP 16

// GEMM tiling (fp16 mma.sync m16n8k16)
#define BM 128
#define BN 128
#define BK 32
#define KSTAGES (DIN / BK)     // 16
#define NSTAGE 4               // cp.async ring depth
#define MAXTILES 272           // sum ceil(cnt_e/128) <= 32768/128 + 16
#define ASTAGE (BM * BK * 2)   // 8192 B
#define BSTAGE (BN * BK * 2)   // 8192 B
#define SMEM_GEMM (NSTAGE * (ASTAGE + BSTAGE) + 1024)   // 66560 B dynamic

// ---------------- device scratch ----------------------------------------------
__device__ int   g_counts[NEXP];
__device__ int   g_tok [NEXP * NTOK];
__device__ int   g_dest[NEXP * NTOK];
__device__ float g_wt  [NEXP * NTOK];
__device__ float g_scratch[(size_t)NTOK * 2 * DOUT];         // 64 MB
__device__ __half g_xh[(size_t)NTOK * DIN];                  // x fp16
__device__ __half g_wth[(size_t)NEXP * DOUT * DIN];          // W^T fp16 [E][DOUT][DIN]

// ---------------- PTX helpers --------------------------------------------------
__device__ __forceinline__ uint32_t smem_u32(const void* p) {
    uint32_t a;
    asm("{ .reg .u64 t; cvta.to.shared.u64 t, %1; cvt.u32.u64 %0, t; }" : "=r"(a) : "l"(p));
    return a;
}
__device__ __forceinline__ void cp16(uint32_t dst, const void* src) {
    asm volatile("cp.async.cg.shared.global [%0], [%1], 16;" :: "r"(dst), "l"(src) : "memory");
}
__device__ __forceinline__ void ldsm_x4(uint32_t* r, uint32_t addr) {
    asm volatile("ldmatrix.sync.aligned.m8n8.x4.shared.b16 {%0,%1,%2,%3}, [%4];"
                 : "=r"(r[0]), "=r"(r[1]), "=r"(r[2]), "=r"(r[3]) : "r"(addr));
}
__device__ __forceinline__ void mma16816(float* d, const uint32_t* a, const uint32_t* b) {
    asm volatile("mma.sync.aligned.m16n8k16.row.col.f32.f16.f16.f32 "
                 "{%0,%1,%2,%3}, {%4,%5,%6,%7}, {%8,%9}, {%0,%1,%2,%3};"
                 : "+f"(d[0]), "+f"(d[1]), "+f"(d[2]), "+f"(d[3])
                 : "r"(a[0]), "r"(a[1]), "r"(a[2]), "r"(a[3]), "r"(b[0]), "r"(b[1]));
}

// ---------------- kernel 0: zero counters -------------------------------------
__global__ void zero_counts_kernel() {
    if (threadIdx.x < NEXP) g_counts[threadIdx.x] = 0;
}

// ---------------- kernel 1: router (exact R1/R7 proven form) -------------------
__global__ void router_kernel(const float* __restrict__ x,
                              const float* __restrict__ gw,
                              const float* __restrict__ gb) {
    int gwarp = (blockIdx.x * blockDim.x + threadIdx.x) >> 5;
    int lane  = threadIdx.x & 31;
    if (gwarp >= NTOK) return;

    const float* xr = x + (size_t)gwarp * DIN;
    float acc[NEXP];
#pragma unroll
    for (int e = 0; e < NEXP; e++) acc[e] = 0.f;

#pragma unroll
    for (int s = 0; s < DIN / 32; s++) {
        int d = s * 32 + lane;
        float xv = __ldg(xr + d);
        const float4* g4 = reinterpret_cast<const float4*>(gw + (size_t)d * NEXP);
        float4 a = __ldg(g4 + 0);
        float4 b = __ldg(g4 + 1);
        float4 c = __ldg(g4 + 2);
        float4 dd = __ldg(g4 + 3);
        acc[0]  += xv * a.x;  acc[1]  += xv * a.y;  acc[2]  += xv * a.z;  acc[3]  += xv * a.w;
        acc[4]  += xv * b.x;  acc[5]  += xv * b.y;  acc[6]  += xv * b.z;  acc[7]  += xv * b.w;
        acc[8]  += xv * c.x;  acc[9]  += xv * c.y;  acc[10] += xv * c.z;  acc[11] += xv * c.w;
        acc[12] += xv * dd.x; acc[13] += xv * dd.y; acc[14] += xv * dd.z; acc[15] += xv * dd.w;
    }
#pragma unroll
    for (int e = 0; e < NEXP; e++) {
#pragma unroll
        for (int off = 16; off > 0; off >>= 1)
            acc[e] += __shfl_xor_sync(0xffffffffu, acc[e], off);
    }
    if (lane == 0) {
        float v[NEXP];
#pragma unroll
        for (int e = 0; e < NEXP; e++) v[e] = acc[e] + gb[e];
        float v0 = v[0]; int e0 = 0;
#pragma unroll
        for (int e = 1; e < NEXP; e++) { if (v[e] > v0) { v0 = v[e]; e0 = e; } }
        float v1 = -3.402823466e38f; int e1 = -1;
#pragma unroll
        for (int e = 0; e < NEXP; e++) { if (e != e0 && v[e] > v1) { v1 = v[e]; e1 = e; } }
        float ex  = expf(v1 - v0);
        float inv = 1.f / (1.f + ex);
        int p0 = atomicAdd(&g_counts[e0], 1);
        g_tok [e0 * NTOK + p0] = gwarp;
        g_dest[e0 * NTOK + p0] = 2 * gwarp;
        g_wt  [e0 * NTOK + p0] = inv;
        int p1 = atomicAdd(&g_counts[e1], 1);
        g_tok [e1 * NTOK + p1] = gwarp;
        g_dest[e1 * NTOK + p1] = 2 * gwarp + 1;
        g_wt  [e1 * NTOK + p1] = ex * inv;
    }
}

// ---------------- kernel 2a: x -> fp16 (exact R7 form) -------------------------
__global__ void convert_x_kernel(const float* __restrict__ x) {
    int idx = blockIdx.x * blockDim.x + threadIdx.x;        // one float4
    float4 v = reinterpret_cast<const float4*>(x)[idx];
    __half2* ph = reinterpret_cast<__half2*>(g_xh);
    ph[idx * 2 + 0] = __floats2half2_rn(v.x, v.y);
    ph[idx * 2 + 1] = __floats2half2_rn(v.z, v.w);
}

// ---------------- kernel 2b: W -> W^T fp16 (K-major) --------------------------
__global__ void convert_w_kernel(const float* __restrict__ ew) {
    __shared__ float tile[32][33];
    int e  = blockIdx.z;
    int d0 = blockIdx.y * 32;     // din tile
    int o0 = blockIdx.x * 32;     // dout tile
    int tx = threadIdx.x & 31, ty = threadIdx.x >> 5;       // 32x8 threads
    const float* src = ew + ((size_t)e * DIN + d0) * DOUT + o0;
#pragma unroll
    for (int i = 0; i < 4; i++)
        tile[ty + i * 8][tx] = src[(size_t)(ty + i * 8) * DOUT + tx];
    __syncthreads();
#pragma unroll
    for (int i = 0; i < 4; i++) {
        int r = ty + i * 8;                       // output row (n) within tile
        float v = tile[tx][r];                    // = W[d0+tx][o0+r]
        g_wth[((size_t)e * DOUT + o0 + r) * DIN + d0 + tx] = __float2half_rn(v);
    }
}

// ---------------- kernel 3: grouped GEMM, 4-stage ring + frag double-buffer ----
__global__ __launch_bounds__(256, 2)
void moe_gemm_kernel(const float* __restrict__ eb) {
    extern __shared__ __align__(16) uint8_t dynsmem[];
    uint8_t* Asm = dynsmem;                                  // NSTAGE * ASTAGE
    uint8_t* Bsm = dynsmem + NSTAGE * ASTAGE;                // NSTAGE * BSTAGE
    int*     stok = reinterpret_cast<int*>(dynsmem + NSTAGE * (ASTAGE + BSTAGE));
    __shared__ int s_e, s_mbase, s_cnt;

    const int tid  = threadIdx.x;
    const int lane = tid & 31;
    const int wid  = tid >> 5;
    const int wm   = (wid & 1) * 64;
    const int wn   = (wid >> 1) * 32;

    if (tid == 0) {
        int b = blockIdx.x, acc = 0, e = -1, mb = 0, cn = 0;
        for (int i = 0; i < NEXP; i++) {
            int c = g_counts[i], t = (c + BM - 1) >> 7;
            if (b < acc + t) { e = i; mb = (b - acc) * BM; cn = c; break; }
            acc += t;
        }
        s_e = e; s_mbase = mb; s_cnt = cn;
    }
    __syncthreads();
    const int e = s_e;
    if (e < 0) return;
    const int mbase = s_mbase, cnt = s_cnt;
    const int nbase = blockIdx.y * BN;

    if (tid < BM) {
        int r = mbase + tid;
        stok[tid] = (r < cnt) ? g_tok[e * NTOK + r] : 0;
    }
    __syncthreads();

    const uint32_t Ab = smem_u32(Asm);
    const uint32_t Bb = smem_u32(Bsm);
    const __half* wtp = g_wth + (size_t)(e * DOUT + nbase) * DIN;

    // cp.async mapping: 512 16B-chunks per tile; thread covers {tid, tid+256}
    auto prefetch = [&](int kt, int buf) {
        int k0 = kt * BK;
#pragma unroll
        for (int t = 0; t < 2; t++) {
            int i = tid + t * 256;
            int r = i >> 2, c = i & 3;
            uint32_t dst = Ab + buf * ASTAGE + r * 64 + ((c ^ ((r >> 1) & 3)) << 4);
            cp16(dst, g_xh + (size_t)stok[r] * DIN + k0 + c * 8);
        }
#pragma unroll
        for (int t = 0; t < 2; t++) {
            int i = tid + t * 256;
            int n = i >> 2, c = i & 3;
            uint32_t dst = Bb + buf * BSTAGE + n * 64 + ((c ^ ((n >> 1) & 3)) << 4);
            cp16(dst, wtp + (size_t)n * DIN + k0 + c * 8);
        }
        asm volatile("cp.async.commit_group;" ::: "memory");
    };

    float acc[4][4][4];
#pragma unroll
    for (int i = 0; i < 4; i++)
#pragma unroll
        for (int j = 0; j < 4; j++)
#pragma unroll
            for (int r = 0; r < 4; r++) acc[i][j][r] = 0.f;

    // lane decomposition for ldmatrix addressing
    const int lrow = (lane & 7) | (((lane >> 3) & 1) << 3);  // row within 16 (A)
    const int akc  = (lane >> 4) & 1;                        // A k-chunk parity
    const int bg   = lane >> 3;                              // B group 0..3
    const int brow = (lane & 7) | ((bg & 2) << 2);           // row within 16 (B)
    const int bkc  = bg & 1;                                 // B k-chunk parity

    prefetch(0, 0);
    prefetch(1, 1);
    prefetch(2, 2);

#pragma unroll 1
    for (int s = 0; s < KSTAGES; s++) {
        int buf = s & 3;
        if (s < KSTAGES - 2)       asm volatile("cp.async.wait_group 2;" ::: "memory");
        else if (s == KSTAGES - 2) asm volatile("cp.async.wait_group 1;" ::: "memory");
        else                       asm volatile("cp.async.wait_group 0;" ::: "memory");
        __syncthreads();   // proves ring slot (s-1)&3 drained of readers
        // issue next loads FIRST: slot (s+3)&3 == (s-1)&3, safe per the barrier above
        if (s + 3 < KSTAGES) prefetch(s + 3, (s + 3) & 3);

        uint32_t abase = Ab + buf * ASTAGE;
        uint32_t bbase = Bb + buf * BSTAGE;

        uint32_t a[2][4][4];   // [kk][mf][reg]
        uint32_t b[2][2][4];   // [kk][p][reg]

        // load fragments for kk=0
#pragma unroll
        for (int mf = 0; mf < 4; mf++) {
            int r = wm + mf * 16 + lrow;
            int c = akc;
            ldsm_x4(a[0][mf], abase + r * 64 + ((c ^ ((r >> 1) & 3)) << 4));
        }
#pragma unroll
        for (int p = 0; p < 2; p++) {
            int n = wn + p * 16 + brow;
            int c = bkc;
            ldsm_x4(b[0][p], bbase + n * 64 + ((c ^ ((n >> 1) & 3)) << 4));
        }

#pragma unroll
        for (int kk = 0; kk < 2; kk++) {
            if (kk == 0) {
                // prefetch kk=1 fragments while kk=0 MMAs issue
#pragma unroll
                for (int mf = 0; mf < 4; mf++) {
                    int r = wm + mf * 16 + lrow;
                    int c = 2 + akc;
                    ldsm_x4(a[1][mf], abase + r * 64 + ((c ^ ((r >> 1) & 3)) << 4));
                }
#pragma unroll
                for (int p = 0; p < 2; p++) {
                    int n = wn + p * 16 + brow;
                    int c = 2 + bkc;
                    ldsm_x4(b[1][p], bbase + n * 64 + ((c ^ ((n >> 1) & 3)) << 4));
                }
            }
#pragma unroll
            for (int mf = 0; mf < 4; mf++)
#pragma unroll
                for (int nf = 0; nf < 4; nf++)
                    mma16816(acc[mf][nf], a[kk][mf], &b[kk][nf >> 1][(nf & 1) * 2]);
        }
    }

    // ---- epilogue: scale by routing weight, add bias, scatter to unique slot --
    const float* ebp = eb + e * DOUT + nbase;
#pragma unroll
    for (int mf = 0; mf < 4; mf++) {
        int rl0 = wm + mf * 16 + (lane >> 2);
#pragma unroll
        for (int h = 0; h < 2; h++) {
            int r = mbase + rl0 + h * 8;
            if (r < cnt) {
                int dst  = g_dest[e * NTOK + r];
                float w  = g_wt [e * NTOK + r];
                float* outp = g_scratch + (size_t)dst * DOUT + nbase;
#pragma unroll
                for (int nf = 0; nf < 4; nf++) {
                    int n = wn + nf * 8 + (lane & 3) * 2;
                    float b0 = ebp[n], b1 = ebp[n + 1];
                    float2 v;
                    v.x = w * (acc[mf][nf][h * 2 + 0] + b0);
                    v.y = w * (acc[mf][nf][h * 2 + 1] + b1);
                    *reinterpret_cast<float2*>(outp + n) = v;
                }
            }
        }
    }
}

// ---------------- kernel 4: combine -------------------------------------------
__global__ void combine_kernel(float* __restrict__ out) {
    int idx = blockIdx.x * blockDim.x + threadIdx.x;   // float4 index
    int t = idx >> 7;
    int c = idx & 127;
    const float4* s = reinterpret_cast<const float4*>(g_scratch);
    float4 a = s[(size_t)t * 256 + c];
    float4 b = s[(size_t)t * 256 + 128 + c];
    float4 r;
    r.x = a.x + b.x; r.y = a.y + b.y; r.z = a.z + b.z; r.w = a.w + b.w;
    reinterpret_cast<float4*>(out)[idx] = r;
}

// ---------------- launch ------------------------------------------------------
extern "C" void kernel_launch(void* const* d_in, const int* in_sizes, int n_in,
                              void* d_out, int out_size) {
    (void)in_sizes; (void)n_in; (void)out_size;
    const float* x  = (const float*)d_in[0];
    const float* gw = (const float*)d_in[1];
    const float* gb = (const float*)d_in[2];
    const float* ew = (const float*)d_in[3];
    const float* eb = (const float*)d_in[4];
    float* out = (float*)d_out;

    cudaFuncSetAttribute(moe_gemm_kernel,
                         cudaFuncAttributeMaxDynamicSharedMemorySize, SMEM_GEMM);

    zero_counts_kernel<<<1, 32>>>();
    router_kernel<<<NTOK / 8, 256>>>(x, gw, gb);
    convert_x_kernel<<<(NTOK * DIN / 4) / 256, 256>>>(x);
    convert_w_kernel<<<dim3(DOUT / 32, DIN / 32, NEXP), 256>>>(ew);
    moe_gemm_kernel<<<dim3(MAXTILES, DOUT / BN), 256, SMEM_GEMM>>>(eb);
    combine_kernel<<<(NTOK * DOUT / 4) / 256, 256>>>(out);
}